// round 5
// baseline (speedup 1.0000x reference)
#include <cuda_runtime.h>
#include <cuda_fp16.h>
#include <cstdint>

#define DT 0.1f
#define TAU_HP 12.3f
#define TAU_LP 2.3f

#define N_NEURONS_MAX 200000
#define N_EDGES_MAX   6400000
#define N_TM1_MAX     25000
#define STEPS_MAX     50

#define GRID_STEP  148
#define TPB_STEP   1024
#define MAX_WAVES  10          // ceil(ceil(175000/148)/128) = 10
#define SCAN_ELEMS 2048        // elements scanned per block in k_scanfill

// ---------------- device scratch (no allocations allowed) ----------------
__device__ int      g_counts[2 * N_NEURONS_MAX];      // per (target, chunk) histogram
__device__ int      g_seg_ptr[2 * N_NEURONS_MAX + 1]; // segment offsets: (row,chunk) lexicographic
__device__ int      g_cursor[2 * N_NEURONS_MAX];      // scatter cursors
__device__ int      g_block_sums[512];
__device__ unsigned g_bar1, g_bar2;                   // grid barriers for k_scanfill
__device__ int2     g_edges[N_EDGES_MAX];             // {local_src, weight_bits}, grouped by (row,chunk)
__device__ __align__(16) float  g_vbuf[2][N_NEURONS_MAX];
__device__ __align__(16) __half g_rbuf[2][N_NEURONS_MAX];
__device__ float    g_table[(STEPS_MAX + 1) * N_TM1_MAX];

// ---------------- setup kernels ----------------

__global__ void k_zero(int n_neurons) {
    int i = blockIdx.x * blockDim.x + threadIdx.x;
    if (i < 2 * n_neurons) g_counts[i] = 0;
    if (i < n_neurons) { g_vbuf[0][i] = 0.0f; g_rbuf[0][i] = __float2half(0.0f); }
    if (i == 0) { g_bar1 = 0; g_bar2 = 0; }
}

// blocks [0,tb): Tm1 filter trajectory; blocks [tb,...): per-(target,chunk) histogram
__global__ void k_tm1hist(const float* __restrict__ x,
                          const int* __restrict__ src, const int* __restrict__ tgt,
                          int n_tm1, int steps, int n_edges, int half, int tb) {
    int bid = blockIdx.x;
    if (bid < tb) {
        int i = bid * blockDim.x + threadIdx.x;
        if (i >= n_tm1) return;
        float f = 0.0f, tv = 0.0f;
        for (int s = 0; s < steps; s++) {
            g_table[s * n_tm1 + i] = tv;
            float xi = x[(long long)s * n_tm1 + i];
            float hp = xi - f;
            f  += DT * hp / TAU_HP;
            tv += DT * (fmaxf(hp, 0.0f) - tv) / TAU_LP;
        }
        g_table[steps * n_tm1 + i] = tv;
    } else {
        int e = (bid - tb) * blockDim.x + threadIdx.x;
        if (e >= n_edges) return;
        int t = tgt[e];
        if (t >= n_tm1) {
            int c = (src[e] >= half) ? 1 : 0;
            atomicAdd(&g_counts[2 * t + c], 1);
        }
    }
}

// Fused scan + fill. All blocks must be co-resident (196 blocks, 2/SM forced).
__global__ void __launch_bounds__(1024, 2)
k_scanfill(const int* __restrict__ src, const int* __restrict__ tgt,
           const float* __restrict__ w,
           int n_edges, int n_tm1, int half, int nseg, int nblocks) {
    __shared__ int sh[1024];
    __shared__ int s_off;
    int tid = threadIdx.x, bid = blockIdx.x;

    // phase A: block-local scan of 2048 histogram entries (2 per thread)
    int i0 = bid * SCAN_ELEMS + tid * 2, i1 = i0 + 1;
    int c0 = (i0 < nseg) ? g_counts[i0] : 0;
    int c1 = (i1 < nseg) ? g_counts[i1] : 0;
    int t = c0 + c1;
    sh[tid] = t;
    __syncthreads();
    #pragma unroll
    for (int o = 1; o < 1024; o <<= 1) {
        int v = (tid >= o) ? sh[tid - o] : 0;
        __syncthreads();
        sh[tid] += v;
        __syncthreads();
    }
    int incl = sh[tid];
    int excl = incl - t;
    if (tid == 1023) g_block_sums[bid] = incl;

    // grid barrier 1
    __threadfence();
    __syncthreads();
    if (tid == 0) {
        atomicAdd(&g_bar1, 1);
        while (((volatile unsigned*)&g_bar1)[0] < (unsigned)nblocks) {}
        __threadfence();
    }
    __syncthreads();

    // phase B: block offset = sum of previous block totals (warp 0)
    if (tid < 32) {
        int p = 0;
        for (int j = tid; j < bid; j += 32) p += g_block_sums[j];
        #pragma unroll
        for (int o = 16; o; o >>= 1) p += __shfl_xor_sync(0xffffffffu, p, o);
        if (tid == 0) s_off = p;
    }
    __syncthreads();
    int off = s_off;
    if (i0 < nseg) { int v0 = off + excl;      g_seg_ptr[i0] = v0; g_cursor[i0] = v0; }
    if (i1 < nseg) { int v1 = off + excl + c0; g_seg_ptr[i1] = v1; g_cursor[i1] = v1; }
    if (bid == nblocks - 1 && tid == 1023) g_seg_ptr[nseg] = off + incl;

    // grid barrier 2
    __threadfence();
    __syncthreads();
    if (tid == 0) {
        atomicAdd(&g_bar2, 1);
        while (((volatile unsigned*)&g_bar2)[0] < (unsigned)nblocks) {}
        __threadfence();
    }
    __syncthreads();

    // phase C: scatter-fill edges (grid-stride)
    int gsz = nblocks * 1024;
    for (int e = bid * 1024 + tid; e < n_edges; e += gsz) {
        int tt = tgt[e];
        if (tt >= n_tm1) {
            int s = src[e];
            int c = (s >= half) ? 1 : 0;
            int pos = atomicAdd(&g_cursor[2 * tt + c], 1);
            g_edges[pos] = make_int2(s - c * half, __float_as_int(w[e]));
        }
    }
}

// ---------------- per-step kernel ----------------
// Persistent 148 blocks. For each source chunk: cooperatively stage the fp16 r
// slice into SMEM (coalesced), then each 8-lane group sums its rows' chunk-local
// edges reading r via LDS. Partial sums carried across chunks in registers.
__global__ void __launch_bounds__(TPB_STEP, 1)
k_step(const float*  __restrict__ vold, float* __restrict__ vnew,
       const __half* __restrict__ rold, __half* __restrict__ rnew,
       const float*  __restrict__ table_next,
       const float*  __restrict__ tau, const float* __restrict__ vrest,
       int n_neurons, int n_tm1, int half) {
    extern __shared__ __half sr[];
    int tid = threadIdx.x, bid = blockIdx.x;
    int group = tid >> 3, lane8 = tid & 7;

    int rows = n_neurons - n_tm1;
    int per = (rows + GRID_STEP - 1) / GRID_STEP;
    int r0 = n_tm1 + bid * per;
    int r1 = min(n_neurons, r0 + per);

    float acc[MAX_WAVES];

    for (int c = 0; c < 2; c++) {
        int base = c * half;
        int csz = min(half, n_neurons - base);
        __syncthreads();   // all groups done reading previous slice
        {   // stage slice -> smem (16B vector loads; tail scalar)
            const int4* s4 = (const int4*)(rold + base);
            int4* d4 = (int4*)sr;
            int n4 = (csz * 2) >> 4;
            for (int i = tid; i < n4; i += TPB_STEP) d4[i] = s4[i];
            for (int i = n4 * 8 + tid; i < csz; i += TPB_STEP) sr[i] = rold[base + i];
        }
        __syncthreads();

        if (c == 0) {
            // Tm1 refresh (independent of smem slice) — share across all blocks
            int tper = (n_tm1 + GRID_STEP - 1) / GRID_STEP;
            int t0 = bid * tper, t1 = min(n_tm1, t0 + tper);
            for (int i = t0 + tid; i < t1; i += TPB_STEP) {
                float tv = table_next[i];
                vnew[i] = tv;
                rnew[i] = __float2half(fmaxf(tv, 0.0f));
            }
        }

        #pragma unroll
        for (int w = 0; w < MAX_WAVES; w++) {
            int row = r0 + w * 128 + group;
            bool active = row < r1;
            int s = 0, e = 0;
            if (active) {
                s = g_seg_ptr[2 * row + c];
                e = g_seg_ptr[2 * row + c + 1];
            }
            float sum = 0.0f;
            int j = s + lane8;
            for (; j + 8 < e; j += 16) {
                int2 a = __ldcs(&g_edges[j]);
                int2 b = __ldcs(&g_edges[j + 8]);
                sum += __int_as_float(a.y) * __half2float(sr[a.x]);
                sum += __int_as_float(b.y) * __half2float(sr[b.x]);
            }
            if (j < e) {
                int2 a = __ldcs(&g_edges[j]);
                sum += __int_as_float(a.y) * __half2float(sr[a.x]);
            }
            // 8-lane reduction (all 32 lanes converged here)
            sum += __shfl_xor_sync(0xffffffffu, sum, 4);
            sum += __shfl_xor_sync(0xffffffffu, sum, 2);
            sum += __shfl_xor_sync(0xffffffffu, sum, 1);
            if (c == 0) {
                acc[w] = sum;
            } else if (active && lane8 == 0) {
                float total = acc[w] + sum;
                float vv = vold[row];
                float vn = vv + DT * ((total - vv + vrest[row]) / tau[row]);
                vnew[row] = vn;
                rnew[row] = __float2half(fmaxf(vn, 0.0f));
            }
        }
    }
}

__global__ void k_out(float* __restrict__ out, const float* __restrict__ vfinal,
                      int n, int n_tm1, int steps) {
    int i = blockIdx.x * blockDim.x + threadIdx.x;
    if (i >= n) return;
    out[i] = (i < n_tm1) ? g_table[(steps - 1) * n_tm1 + i] : vfinal[i];
}

// ---------------- launch ----------------

extern "C" void kernel_launch(void* const* d_in, const int* in_sizes, int n_in,
                              void* d_out, int out_size) {
    const float* tm1_input = (const float*)d_in[0];   // [steps, n_tm1]
    const float* weights   = (const float*)d_in[1];   // [n_edges]
    const float* tau       = (const float*)d_in[2];   // [n_neurons]
    const float* vrest     = (const float*)d_in[3];   // [n_neurons]
    const int*   src       = (const int*)  d_in[4];   // [n_edges]
    const int*   tgt       = (const int*)  d_in[5];   // [n_edges]

    const int n_tm1     = 25000;
    const int n_edges   = in_sizes[1];
    const int n_neurons = in_sizes[2];
    const int steps     = in_sizes[0] / n_tm1;

    const int half = (n_neurons + 1) / 2;             // 100000 -> 200KB fp16 slice
    const int nseg = 2 * n_neurons;
    const int smem_bytes = half * (int)sizeof(__half);

    cudaFuncSetAttribute(k_step, cudaFuncAttributeMaxDynamicSharedMemorySize, smem_bytes);

    // setup: exactly 3 launches so the first k_step lands in the ncu capture window
    k_zero<<<(nseg + 255) / 256, 256>>>(n_neurons);
    int tb = (n_tm1 + 255) / 256;
    int eb = (n_edges + 255) / 256;
    k_tm1hist<<<tb + eb, 256>>>(tm1_input, src, tgt, n_tm1, steps, n_edges, half, tb);
    int scan_blocks = (nseg + SCAN_ELEMS - 1) / SCAN_ELEMS;   // 196 (all co-resident)
    k_scanfill<<<scan_blocks, 1024>>>(src, tgt, weights, n_edges, n_tm1, half,
                                      nseg, scan_blocks);

    float*  vbase = nullptr;
    __half* rbase = nullptr;
    float*  tbl   = nullptr;
    cudaGetSymbolAddress((void**)&vbase, g_vbuf);
    cudaGetSymbolAddress((void**)&rbase, g_rbuf);
    cudaGetSymbolAddress((void**)&tbl,   g_table);

    for (int st = 0; st < steps; st++) {
        const float*  vold = vbase + (size_t)(st & 1) * N_NEURONS_MAX;
        float*        vnew = vbase + (size_t)((st + 1) & 1) * N_NEURONS_MAX;
        const __half* rold = rbase + (size_t)(st & 1) * N_NEURONS_MAX;
        __half*       rnew = rbase + (size_t)((st + 1) & 1) * N_NEURONS_MAX;
        const float*  table_next = tbl + (size_t)(st + 1) * n_tm1;
        k_step<<<GRID_STEP, TPB_STEP, smem_bytes>>>(vold, vnew, rold, rnew,
                                                    table_next, tau, vrest,
                                                    n_neurons, n_tm1, half);
    }

    const float* vfinal = vbase + (size_t)(steps & 1) * N_NEURONS_MAX;
    k_out<<<(out_size + 255) / 256, 256>>>((float*)d_out, vfinal,
                                           out_size, n_tm1, steps);
}

// round 7
// speedup vs baseline: 1.4938x; 1.4938x over previous
#include <cuda_runtime.h>
#include <cuda_fp16.h>
#include <cstdint>

#define DT 0.1f
#define TAU_HP 12.3f
#define TAU_LP 2.3f

#define N_NEURONS_MAX 200000
#define N_EDGES_MAX   6400000
#define N_TM1_MAX     25000
#define STEPS_MAX     50

#define GRID_STEP  148
#define TPB_STEP   1024
#define LANES      4
#define GROUPS     (TPB_STEP / LANES)   // 256 rows per wave
#define MAX_WAVES  5                    // ceil(ceil(175000/148)/256) = 5
#define SCAN_ELEMS 2048

// ---------------- device scratch (no allocations allowed) ----------------
__device__ int      g_counts[2 * N_NEURONS_MAX];      // per (target, chunk) histogram
__device__ int      g_seg_ptr[2 * N_NEURONS_MAX + 1]; // segment offsets, (row,chunk) lexicographic
__device__ int      g_cursor[2 * N_NEURONS_MAX];      // scatter cursors
__device__ int      g_block_sums[512];
__device__ unsigned g_bar1, g_bar2;                   // grid barriers for k_scanfill
__device__ int2     g_edges[N_EDGES_MAX];             // {local_src, weight_bits}
__device__ __align__(16) float  g_vbuf[2][N_NEURONS_MAX];
__device__ __align__(16) __half g_rbuf[2][N_NEURONS_MAX];
__device__ float    g_table[(STEPS_MAX + 1) * N_TM1_MAX];

// ---------------- setup kernels ----------------

__global__ void k_zero(int n_neurons) {
    int i = blockIdx.x * blockDim.x + threadIdx.x;
    if (i < 2 * n_neurons) g_counts[i] = 0;
    if (i < n_neurons) { g_vbuf[0][i] = 0.0f; g_rbuf[0][i] = __float2half(0.0f); }
    if (i == 0) { g_bar1 = 0; g_bar2 = 0; }
}

// blocks [0,tb): Tm1 filter trajectory; blocks [tb,...): per-(target,chunk) histogram
__global__ void k_tm1hist(const float* __restrict__ x,
                          const int* __restrict__ src, const int* __restrict__ tgt,
                          int n_tm1, int steps, int n_edges, int half, int tb) {
    int bid = blockIdx.x;
    if (bid < tb) {
        int i = bid * blockDim.x + threadIdx.x;
        if (i >= n_tm1) return;
        float f = 0.0f, tv = 0.0f;
        for (int s = 0; s < steps; s++) {
            g_table[s * n_tm1 + i] = tv;
            float xi = x[(long long)s * n_tm1 + i];
            float hp = xi - f;
            f  += DT * hp / TAU_HP;
            tv += DT * (fmaxf(hp, 0.0f) - tv) / TAU_LP;
        }
        g_table[steps * n_tm1 + i] = tv;
    } else {
        int e = (bid - tb) * blockDim.x + threadIdx.x;
        if (e >= n_edges) return;
        int t = tgt[e];
        if (t >= n_tm1) {
            int c = (src[e] >= half) ? 1 : 0;
            atomicAdd(&g_counts[2 * t + c], 1);
        }
    }
}

// Fused scan + fill. All 196 blocks co-resident (2/SM forced).
__global__ void __launch_bounds__(1024, 2)
k_scanfill(const int* __restrict__ src, const int* __restrict__ tgt,
           const float* __restrict__ w,
           int n_edges, int n_tm1, int half, int nseg, int nblocks) {
    __shared__ int sh[1024];
    __shared__ int s_off;
    int tid = threadIdx.x, bid = blockIdx.x;

    // phase A: block-local scan of 2048 histogram entries (2 per thread)
    int i0 = bid * SCAN_ELEMS + tid * 2, i1 = i0 + 1;
    int c0 = (i0 < nseg) ? g_counts[i0] : 0;
    int c1 = (i1 < nseg) ? g_counts[i1] : 0;
    int t = c0 + c1;
    sh[tid] = t;
    __syncthreads();
    #pragma unroll
    for (int o = 1; o < 1024; o <<= 1) {
        int v = (tid >= o) ? sh[tid - o] : 0;
        __syncthreads();
        sh[tid] += v;
        __syncthreads();
    }
    int incl = sh[tid];
    int excl = incl - t;
    if (tid == 1023) g_block_sums[bid] = incl;

    // grid barrier 1
    __threadfence();
    __syncthreads();
    if (tid == 0) {
        atomicAdd(&g_bar1, 1);
        while (((volatile unsigned*)&g_bar1)[0] < (unsigned)nblocks) {}
        __threadfence();
    }
    __syncthreads();

    // phase B: block offset = sum of previous block totals
    if (tid < 32) {
        int p = 0;
        for (int j = tid; j < bid; j += 32) p += g_block_sums[j];
        #pragma unroll
        for (int o = 16; o; o >>= 1) p += __shfl_xor_sync(0xffffffffu, p, o);
        if (tid == 0) s_off = p;
    }
    __syncthreads();
    int off = s_off;
    if (i0 < nseg) { int v0 = off + excl;      g_seg_ptr[i0] = v0; g_cursor[i0] = v0; }
    if (i1 < nseg) { int v1 = off + excl + c0; g_seg_ptr[i1] = v1; g_cursor[i1] = v1; }
    if (bid == nblocks - 1 && tid == 1023) g_seg_ptr[nseg] = off + incl;

    // grid barrier 2
    __threadfence();
    __syncthreads();
    if (tid == 0) {
        atomicAdd(&g_bar2, 1);
        while (((volatile unsigned*)&g_bar2)[0] < (unsigned)nblocks) {}
        __threadfence();
    }
    __syncthreads();

    // phase C: scatter-fill edges (grid-stride)
    int gsz = nblocks * 1024;
    for (int e = bid * 1024 + tid; e < n_edges; e += gsz) {
        int tt = tgt[e];
        if (tt >= n_tm1) {
            int s = src[e];
            int c = (s >= half) ? 1 : 0;
            int pos = atomicAdd(&g_cursor[2 * tt + c], 1);
            g_edges[pos] = make_int2(s - c * half, __float_as_int(w[e]));
        }
    }
}

// ---------------- per-step kernel ----------------
// 148 persistent-shape blocks. For each of 2 source chunks: stage the fp16 r
// slice (200KB) into SMEM, then 4-lane groups sum their rows' chunk-local
// edges with LDS gathers. Edges use plain __ldg so they stay L2-resident
// across steps (NO streaming hint — that was R5's DRAM regression).
__global__ void __launch_bounds__(TPB_STEP, 1)
k_step(const float*  __restrict__ vold, float* __restrict__ vnew,
       const __half* __restrict__ rold, __half* __restrict__ rnew,
       const float*  __restrict__ table_next,
       const float*  __restrict__ tau, const float* __restrict__ vrest,
       int n_neurons, int n_tm1, int half) {
    extern __shared__ __half sr[];
    int tid = threadIdx.x, bid = blockIdx.x;
    int group = tid >> 2, lane = tid & 3;           // 256 groups of 4 lanes

    int rows = n_neurons - n_tm1;
    int per = (rows + GRID_STEP - 1) / GRID_STEP;
    int r0 = n_tm1 + bid * per;
    int r1 = min(n_neurons, r0 + per);

    float acc[MAX_WAVES];

    #pragma unroll
    for (int c = 0; c < 2; c++) {
        int base = c * half;
        int csz = min(half, n_neurons - base);
        __syncthreads();   // all groups done reading previous slice
        {   // stage slice -> smem (16B vector loads; tail scalar)
            const int4* s4 = (const int4*)(rold + base);
            int4* d4 = (int4*)sr;
            int n4 = (csz * 2) >> 4;
            for (int i = tid; i < n4; i += TPB_STEP) d4[i] = s4[i];
            for (int i = n4 * 8 + tid; i < csz; i += TPB_STEP) sr[i] = rold[base + i];
        }
        __syncthreads();

        if (c == 0) {
            // Tm1 refresh (independent of smem slice)
            int tper = (n_tm1 + GRID_STEP - 1) / GRID_STEP;
            int t0 = bid * tper, t1 = min(n_tm1, t0 + tper);
            for (int i = t0 + tid; i < t1; i += TPB_STEP) {
                float tv = table_next[i];
                vnew[i] = tv;
                rnew[i] = __float2half(fmaxf(tv, 0.0f));
            }
        }

        #pragma unroll
        for (int w = 0; w < MAX_WAVES; w++) {
            int row = r0 + w * GROUPS + group;
            bool active = row < r1;
            int s = 0, e = 0;
            if (active) {
                s = __ldg(&g_seg_ptr[2 * row + c]);
                e = __ldg(&g_seg_ptr[2 * row + c + 1]);
            }
            float sum = 0.0f;
            int j = s + lane;
            // 4-way unroll: 4 independent L2 edge loads + 4 LDS in flight
            for (; j + 12 < e; j += 16) {
                int2 e0 = __ldg(&g_edges[j]);
                int2 e1 = __ldg(&g_edges[j + 4]);
                int2 e2 = __ldg(&g_edges[j + 8]);
                int2 e3 = __ldg(&g_edges[j + 12]);
                float r0f = __half2float(sr[e0.x]);
                float r1f = __half2float(sr[e1.x]);
                float r2f = __half2float(sr[e2.x]);
                float r3f = __half2float(sr[e3.x]);
                sum += __int_as_float(e0.y) * r0f;
                sum += __int_as_float(e1.y) * r1f;
                sum += __int_as_float(e2.y) * r2f;
                sum += __int_as_float(e3.y) * r3f;
            }
            for (; j < e; j += 4) {
                int2 ed = __ldg(&g_edges[j]);
                sum += __int_as_float(ed.y) * __half2float(sr[ed.x]);
            }
            // 4-lane reduction (all 32 lanes converged here)
            sum += __shfl_xor_sync(0xffffffffu, sum, 2);
            sum += __shfl_xor_sync(0xffffffffu, sum, 1);
            if (c == 0) {
                acc[w] = sum;
            } else if (active && lane == 0) {
                float total = acc[w] + sum;
                float vv = vold[row];
                float vn = vv + DT * ((total - vv + vrest[row]) / tau[row]);
                vnew[row] = vn;
                rnew[row] = __float2half(fmaxf(vn, 0.0f));
            }
        }
    }
}

__global__ void k_out(float* __restrict__ out, const float* __restrict__ vfinal,
                      int n, int n_tm1, int steps) {
    int i = blockIdx.x * blockDim.x + threadIdx.x;
    if (i >= n) return;
    out[i] = (i < n_tm1) ? g_table[(steps - 1) * n_tm1 + i] : vfinal[i];
}

// ---------------- launch ----------------

extern "C" void kernel_launch(void* const* d_in, const int* in_sizes, int n_in,
                              void* d_out, int out_size) {
    const float* tm1_input = (const float*)d_in[0];   // [steps, n_tm1]
    const float* weights   = (const float*)d_in[1];   // [n_edges]
    const float* tau       = (const float*)d_in[2];   // [n_neurons]
    const float* vrest     = (const float*)d_in[3];   // [n_neurons]
    const int*   src       = (const int*)  d_in[4];   // [n_edges]
    const int*   tgt       = (const int*)  d_in[5];   // [n_edges]

    const int n_tm1     = 25000;
    const int n_edges   = in_sizes[1];
    const int n_neurons = in_sizes[2];
    const int steps     = in_sizes[0] / n_tm1;

    const int half = (n_neurons + 1) / 2;             // 100000 -> 200KB fp16 slice
    const int nseg = 2 * n_neurons;
    const int smem_bytes = half * (int)sizeof(__half);

    cudaFuncSetAttribute(k_step, cudaFuncAttributeMaxDynamicSharedMemorySize, smem_bytes);

    // setup: exactly 3 launches so k_step lands in the ncu capture window
    k_zero<<<(nseg + 255) / 256, 256>>>(n_neurons);
    int tb = (n_tm1 + 255) / 256;
    int eb = (n_edges + 255) / 256;
    k_tm1hist<<<tb + eb, 256>>>(tm1_input, src, tgt, n_tm1, steps, n_edges, half, tb);
    int scan_blocks = (nseg + SCAN_ELEMS - 1) / SCAN_ELEMS;   // 196 (all co-resident)
    k_scanfill<<<scan_blocks, 1024>>>(src, tgt, weights, n_edges, n_tm1, half,
                                      nseg, scan_blocks);

    float*  vbase = nullptr;
    __half* rbase = nullptr;
    float*  tbl   = nullptr;
    cudaGetSymbolAddress((void**)&vbase, g_vbuf);
    cudaGetSymbolAddress((void**)&rbase, g_rbuf);
    cudaGetSymbolAddress((void**)&tbl,   g_table);

    for (int st = 0; st < steps; st++) {
        const float*  vold = vbase + (size_t)(st & 1) * N_NEURONS_MAX;
        float*        vnew = vbase + (size_t)((st + 1) & 1) * N_NEURONS_MAX;
        const __half* rold = rbase + (size_t)(st & 1) * N_NEURONS_MAX;
        __half*       rnew = rbase + (size_t)((st + 1) & 1) * N_NEURONS_MAX;
        const float*  table_next = tbl + (size_t)(st + 1) * n_tm1;
        k_step<<<GRID_STEP, TPB_STEP, smem_bytes>>>(vold, vnew, rold, rnew,
                                                    table_next, tau, vrest,
                                                    n_neurons, n_tm1, half);
    }

    const float* vfinal = vbase + (size_t)(steps & 1) * N_NEURONS_MAX;
    k_out<<<(out_size + 255) / 256, 256>>>((float*)d_out, vfinal,
                                           out_size, n_tm1, steps);
}